// round 15
// baseline (speedup 1.0000x reference)
#include <cuda_runtime.h>
#include <cuda_bf16.h>
#include <cuda_fp16.h>
#include <cstdint>

// Problem constants
#define B_   16
#define TE_  128
#define TD_  128
#define H_   256

// Scratch (device globals)
__device__ float g_ortho[B_ * TE_ * H_];   // enc - cumsum_excl(enc)
__device__ float g_was  [B_ * TE_ * H_];   // scanned enc@Wa
__device__ float g_uah  [B_ * TD_ * H_];   // dec @ U_a

__device__ __forceinline__ float tanh_fast(float x) {
    float y;
    asm("tanh.approx.f32 %0, %1;" : "=f"(y) : "f"(x));
    return y;
}

__device__ __forceinline__ void mma_tf32(float c[4],
                                         uint32_t a0, uint32_t a1, uint32_t a2, uint32_t a3,
                                         uint32_t b0, uint32_t b1) {
    asm volatile(
        "mma.sync.aligned.m16n8k8.row.col.f32.tf32.tf32.f32 "
        "{%0,%1,%2,%3}, {%4,%5,%6,%7}, {%8,%9}, {%0,%1,%2,%3};"
        : "+f"(c[0]), "+f"(c[1]), "+f"(c[2]), "+f"(c[3])
        : "r"(a0), "r"(a1), "r"(a2), "r"(a3), "r"(b0), "r"(b1));
}

__device__ __forceinline__ void tf32_split(float x, float& hf, float& lf) {
    uint32_t h;
    asm("cvt.rna.tf32.f32 %0, %1;" : "=r"(h) : "f"(x));
    hf = __uint_as_float(h);
    float l = x - hf;
    uint32_t lo;
    asm("cvt.rna.tf32.f32 %0, %1;" : "=r"(lo) : "f"(l));
    lf = __uint_as_float(lo);
}

// ---------------------------------------------------------------------------
// Scan unit: out[b, t, hg*32+hl] = in[b,t,..] - sum_{t'<t} in[b,t',..]
// ---------------------------------------------------------------------------
__device__ __forceinline__ void scan_block(const float* __restrict__ in,
                                           float* __restrict__ out,
                                           int b, int hg, float* sm) {
    const int tid  = threadIdx.x;
    const int warp = tid >> 5;
    const int lane = tid & 31;

    const float* base = in + (b * TE_) * H_ + hg * 32;
#pragma unroll
    for (int k = 0; k < 16; k++) {
        int idx = tid + k * 256;
        int t = idx >> 5, hl = idx & 31;
        sm[t * 33 + hl] = base[t * H_ + hl];
    }
    __syncthreads();

#pragma unroll
    for (int c = 0; c < 4; c++) {
        int h = warp * 4 + c;
        float a0 = sm[(4 * lane + 0) * 33 + h];
        float a1 = sm[(4 * lane + 1) * 33 + h];
        float a2 = sm[(4 * lane + 2) * 33 + h];
        float a3 = sm[(4 * lane + 3) * 33 + h];
        float L = (a0 + a1) + (a2 + a3);
        float sc = L;
#pragma unroll
        for (int o = 1; o < 32; o <<= 1) {
            float v = __shfl_up_sync(0xffffffffu, sc, o);
            if (lane >= o) sc += v;
        }
        float p = sc - L;
        float o0 = a0 - p; p += a0;
        float o1 = a1 - p; p += a1;
        float o2 = a2 - p; p += a2;
        float o3 = a3 - p;
        sm[(4 * lane + 0) * 33 + h] = o0;
        sm[(4 * lane + 1) * 33 + h] = o1;
        sm[(4 * lane + 2) * 33 + h] = o2;
        sm[(4 * lane + 3) * 33 + h] = o3;
    }
    __syncthreads();

    float* obase = out + (b * TE_) * H_ + hg * 32;
#pragma unroll
    for (int k = 0; k < 16; k++) {
        int idx = tid + k * 256;
        int t = idx >> 5, hl = idx & 31;
        obase[t * H_ + hl] = sm[t * 33 + hl];
    }
}

// ---------------------------------------------------------------------------
// K1, 1-D grid of 384 x 256 threads:
//   bid [0,128):   g_was = scan(enc @ Wa); 128x32 tf32 tile + scan epilogue
//   bid [128,256): g_uah = dec @ Ua;       128x32 tf32 tile
//   bid [256,384): g_ortho scan, one 32-col unit per block
// Warp tile 16x32 (8 warps cover M=128), m16n8k8 with 3xTF32 hi/lo.
// ---------------------------------------------------------------------------
__global__ __launch_bounds__(256) void k1_kernel(const float* __restrict__ enc,
                                                 const float* __restrict__ dec,
                                                 const float* __restrict__ Wa,
                                                 const float* __restrict__ Ua) {
    __shared__ __align__(16) float sm[6400];   // 25.6KB multi-purpose
    const int bid = blockIdx.x;
    const int tid = threadIdx.x;

    if (bid >= 256) {                          // ---- ortho scans ----
        int lin = bid - 256;                   // 0..127
        scan_block(enc, g_ortho, lin >> 3, lin & 7, sm);
        return;
    }

    const int z = (bid >= 128) ? 1 : 0;
    const int local = bid & 127;
    const float* A = z ? dec : enc;
    const float* W = z ? Ua  : Wa;

    // smem: Ah[128][20]@0, Al@2560, Bh[16][40]@5120, Bl@5760
    float* Ah = sm;
    float* Al = sm + 2560;
    float* Bh = sm + 5120;
    float* Bl = sm + 5760;

    const int bm = (local >> 3) * 128;         // batch * 128
    const int bn = (local & 7) * 32;
    const int warp = tid >> 5;
    const int lane = tid & 31;
    const int g = lane >> 2;                   // 0..7
    const int t = lane & 3;                    // 0..3
    const int m0 = warp * 16;

    // Loader coords
    const int ar  = tid >> 1;                  // A row 0..127
    const int akh = (tid & 1) * 8;
    const int bkr = tid >> 4;                  // B k-row 0..15
    const int bc2 = (tid & 15) * 2;            // B col pair

    float acc[4][4];
#pragma unroll
    for (int na = 0; na < 4; na++)
#pragma unroll
        for (int j = 0; j < 4; j++) acc[na][j] = 0.0f;

    float4 pA0, pA1;
    float2 pB;
    pA0 = *(const float4*)&A[(bm + ar) * 256 + akh];
    pA1 = *(const float4*)&A[(bm + ar) * 256 + akh + 4];
    pB  = *(const float2*)&W[bkr * 256 + bn + bc2];

    auto sts_tiles = [&](float4 a0v, float4 a1v, float2 bv) {
        float4 h, l;
        tf32_split(a0v.x, h.x, l.x); tf32_split(a0v.y, h.y, l.y);
        tf32_split(a0v.z, h.z, l.z); tf32_split(a0v.w, h.w, l.w);
        *(float4*)&Ah[ar * 20 + akh] = h;  *(float4*)&Al[ar * 20 + akh] = l;
        tf32_split(a1v.x, h.x, l.x); tf32_split(a1v.y, h.y, l.y);
        tf32_split(a1v.z, h.z, l.z); tf32_split(a1v.w, h.w, l.w);
        *(float4*)&Ah[ar * 20 + akh + 4] = h;  *(float4*)&Al[ar * 20 + akh + 4] = l;
        float2 hb, lb;
        tf32_split(bv.x, hb.x, lb.x); tf32_split(bv.y, hb.y, lb.y);
        *(float2*)&Bh[bkr * 40 + bc2] = hb;  *(float2*)&Bl[bkr * 40 + bc2] = lb;
    };

    sts_tiles(pA0, pA1, pB);
    __syncthreads();

#pragma unroll 1
    for (int kt = 0; kt < 16; kt++) {
        if (kt < 15) {
            int k0 = (kt + 1) * 16;
            pA0 = *(const float4*)&A[(bm + ar) * 256 + k0 + akh];
            pA1 = *(const float4*)&A[(bm + ar) * 256 + k0 + akh + 4];
            pB  = *(const float2*)&W[(k0 + bkr) * 256 + bn + bc2];
        }
#pragma unroll
        for (int ka = 0; ka < 2; ka++) {
            const int kb = ka * 8 + t;
            const int r = m0 + g;
            uint32_t ah0 = __float_as_uint(Ah[r * 20 + kb]);
            uint32_t ah1 = __float_as_uint(Ah[(r + 8) * 20 + kb]);
            uint32_t ah2 = __float_as_uint(Ah[r * 20 + kb + 4]);
            uint32_t ah3 = __float_as_uint(Ah[(r + 8) * 20 + kb + 4]);
            uint32_t al0 = __float_as_uint(Al[r * 20 + kb]);
            uint32_t al1 = __float_as_uint(Al[(r + 8) * 20 + kb]);
            uint32_t al2 = __float_as_uint(Al[r * 20 + kb + 4]);
            uint32_t al3 = __float_as_uint(Al[(r + 8) * 20 + kb + 4]);
#pragma unroll
            for (int na = 0; na < 4; na++) {
                int n = na * 8 + g;
                uint32_t bh0 = __float_as_uint(Bh[kb * 40 + n]);
                uint32_t bh1 = __float_as_uint(Bh[(kb + 4) * 40 + n]);
                uint32_t bl0 = __float_as_uint(Bl[kb * 40 + n]);
                uint32_t bl1 = __float_as_uint(Bl[(kb + 4) * 40 + n]);
                mma_tf32(acc[na], ah0, ah1, ah2, ah3, bh0, bh1);
                mma_tf32(acc[na], al0, al1, al2, al3, bh0, bh1);
                mma_tf32(acc[na], ah0, ah1, ah2, ah3, bl0, bl1);
            }
        }
        __syncthreads();
        if (kt < 15) {
            sts_tiles(pA0, pA1, pB);
            __syncthreads();
        }
    }

    if (z == 1) {
#pragma unroll
        for (int na = 0; na < 4; na++) {
            int r = bm + m0 + g;
            int c = bn + na * 8 + 2 * t;
            float2 lo2 = {acc[na][0], acc[na][1]};
            float2 hi2 = {acc[na][2], acc[na][3]};
            *(float2*)&g_uah[r * 256 + c]       = lo2;
            *(float2*)&g_uah[(r + 8) * 256 + c] = hi2;
        }
        return;
    }

    // z == 0: fused scan epilogue, cols bn..bn+31, rows 0..127 (stride 33)
    float* sb = sm;
#pragma unroll
    for (int na = 0; na < 4; na++) {
        int r = m0 + g;
        int c = na * 8 + 2 * t;
        sb[r * 33 + c]       = acc[na][0];
        sb[r * 33 + c + 1]   = acc[na][1];
        sb[(r + 8) * 33 + c]     = acc[na][2];
        sb[(r + 8) * 33 + c + 1] = acc[na][3];
    }
    __syncthreads();

#pragma unroll
    for (int c = 0; c < 4; c++) {
        int col = warp * 4 + c;
        float a0 = sb[(4 * lane + 0) * 33 + col];
        float a1 = sb[(4 * lane + 1) * 33 + col];
        float a2 = sb[(4 * lane + 2) * 33 + col];
        float a3 = sb[(4 * lane + 3) * 33 + col];
        float L = (a0 + a1) + (a2 + a3);
        float sc = L;
#pragma unroll
        for (int o = 1; o < 32; o <<= 1) {
            float v = __shfl_up_sync(0xffffffffu, sc, o);
            if (lane >= o) sc += v;
        }
        float p = sc - L;
        float o0 = a0 - p; p += a0;
        float o1 = a1 - p; p += a1;
        float o2 = a2 - p; p += a2;
        float o3 = a3 - p;
        sb[(4 * lane + 0) * 33 + col] = o0;
        sb[(4 * lane + 1) * 33 + col] = o1;
        sb[(4 * lane + 2) * 33 + col] = o2;
        sb[(4 * lane + 3) * 33 + col] = o3;
    }
    __syncthreads();

#pragma unroll
    for (int k = 0; k < 16; k++) {
        int idx = tid + k * 256;
        int t2 = idx >> 5, c = idx & 31;
        g_was[(bm + t2) * 256 + bn + c] = sb[t2 * 33 + c];
    }
}

// ---------------------------------------------------------------------------
// K2: energies + softmax (R13 best version, f32 tanh, direct LDG).
// Block = (b, tile of 4 d), 512 threads = 16 warps.
// ---------------------------------------------------------------------------
__global__ __launch_bounds__(512) void energy_kernel(const float* __restrict__ Va,
                                                     float* __restrict__ e_out) {
    const int b    = blockIdx.y;
    const int d0   = blockIdx.x * 4;
    const int tid  = threadIdx.x;
    const int warp = tid >> 5;
    const int lane = tid & 31;
    const int wd   = warp & 3;
    const int eq   = warp >> 2;

    __shared__ float part[16][16][33];
    __shared__ float en_s[4][TE_];

    const int d = d0 + wd;

    const float4 v0 = *(const float4*)(Va + 4 * lane);
    const float4 v1 = *(const float4*)(Va + 128 + 4 * lane);
    const float* urow = g_uah + ((b * TD_) + d) * H_;
    const float4 u0 = *(const float4*)(urow + 4 * lane);
    const float4 u1 = *(const float4*)(urow + 128 + 4 * lane);

    const float* wbase = g_was + (b * TE_) * H_;
    const int ebase = eq * 32;

#pragma unroll
    for (int c0 = 0; c0 < 32; c0 += 16) {
#pragma unroll 4
        for (int el = 0; el < 16; el++) {
            const float* wr = wbase + (ebase + c0 + el) * H_;
            float4 w0 = *(const float4*)(wr + 4 * lane);
            float4 w1 = *(const float4*)(wr + 128 + 4 * lane);
            float s = tanh_fast(w0.x + u0.x) * v0.x;
            s = fmaf(tanh_fast(w0.y + u0.y), v0.y, s);
            s = fmaf(tanh_fast(w0.z + u0.z), v0.z, s);
            s = fmaf(tanh_fast(w0.w + u0.w), v0.w, s);
            s = fmaf(tanh_fast(w1.x + u1.x), v1.x, s);
            s = fmaf(tanh_fast(w1.y + u1.y), v1.y, s);
            s = fmaf(tanh_fast(w1.z + u1.z), v1.z, s);
            s = fmaf(tanh_fast(w1.w + u1.w), v1.w, s);
            part[warp][el][lane] = s;
        }
        __syncwarp();
        if (lane < 16) {
            float s = 0.0f;
#pragma unroll
            for (int j = 0; j < 32; j++) s += part[warp][lane][j];
            en_s[wd][ebase + c0 + lane] = s;
        }
        __syncwarp();
    }
    __syncthreads();

    if (warp < 4) {
        float v0s = en_s[wd][lane];
        float v1s = en_s[wd][lane + 32];
        float v2s = en_s[wd][lane + 64];
        float v3s = en_s[wd][lane + 96];
        float m = fmaxf(fmaxf(v0s, v1s), fmaxf(v2s, v3s));
#pragma unroll
        for (int o = 16; o > 0; o >>= 1)
            m = fmaxf(m, __shfl_xor_sync(0xffffffffu, m, o));
        float e0v = __expf(v0s - m), e1v = __expf(v1s - m);
        float e2v = __expf(v2s - m), e3v = __expf(v3s - m);
        float s = e0v + e1v + e2v + e3v;
#pragma unroll
        for (int o = 16; o > 0; o >>= 1)
            s += __shfl_xor_sync(0xffffffffu, s, o);
        float inv = __fdividef(1.0f, s);
        float* eo = e_out + ((b * TD_) + d) * TE_;
        eo[lane]      = e0v * inv;
        eo[lane + 32] = e1v * inv;
        eo[lane + 64] = e2v * inv;
        eo[lane + 96] = e3v * inv;
    }
}

// ---------------------------------------------------------------------------
// K3: context batched GEMM.  c_out[b] = P[b] (TD x TE) @ g_ortho[b] (TE x H)
// ---------------------------------------------------------------------------
__global__ __launch_bounds__(256) void ctx_kernel(const float* __restrict__ P,
                                                  float* __restrict__ c_out) {
    __shared__ __align__(16) float sm2[2 * 16 * 68 * 2];

    float (*As)[68] = (float (*)[68])sm2;
    float (*Bs)[68] = (float (*)[68])(sm2 + 2 * 16 * 68);

    const int bz = blockIdx.z;
    const int bm = blockIdx.y * 64;
    const int bn = blockIdx.x * 64;
    const int tid = threadIdx.x;
    const int tr = tid >> 4;
    const int tc = tid & 15;

    const float* A = P       + bz * TD_ * TE_;
    const float* W = g_ortho + bz * TE_ * H_;
    float*       C = c_out   + bz * TD_ * H_;

    const int r0 = tid >> 2;
    const int qa = tid & 3;
    const int lbk = tid >> 4;
    const int lbq = tid & 15;

    float acc[4][4];
#pragma unroll
    for (int i = 0; i < 4; i++)
#pragma unroll
        for (int j = 0; j < 4; j++) acc[i][j] = 0.0f;

    float4 pa = *(const float4*)&A[(bm + r0) * TE_ + qa * 4];
    float4 pb = *(const float4*)&W[lbk * H_ + bn + lbq * 4];
    As[qa * 4 + 0][r0] = pa.x;  As[qa * 4 + 1][r0] = pa.y;
    As[qa * 4 + 2][r0] = pa.z;  As[qa * 4 + 3][r0] = pa.w;
    *(float4*)&Bs[lbk][lbq * 4] = pb;
    __syncthreads();

#pragma unroll 1
    for (int kt = 0; kt < 8; kt++) {
        if (kt < 7) {
            int k0 = (kt + 1) * 16;
            pa = *(const float4*)&A[(bm + r0) * TE_ + k0 + qa * 4];
            pb = *(const float4*)&W[(k0 + lbk) * H_ + bn + lbq * 4];
        }
        const int cb = (kt & 1) * 16;
#pragma unroll
        for (int kk = 0; kk < 16; kk++) {
            float4 a4 = *(const float4*)&As[cb + kk][tr * 4];
            float4 b4 = *(const float4*)&Bs[cb + kk][tc * 4];
            acc[0][0] = fmaf(a4.x, b4.x, acc[0][0]);
            acc[0][1] = fmaf(a4.x, b4.y, acc[0][1]);
            acc[0][2] = fmaf(a4.x, b4.z, acc[0][2]);
            acc[0][3] = fmaf(a4.x, b4.w, acc[0][3]);
            acc[1][0] = fmaf(a4.y, b4.x, acc[1][0]);
            acc[1][1] = fmaf(a4.y, b4.y, acc[1][1]);
            acc[1][2] = fmaf(a4.y, b4.z, acc[1][2]);
            acc[1][3] = fmaf(a4.y, b4.w, acc[1][3]);
            acc[2][0] = fmaf(a4.z, b4.x, acc[2][0]);
            acc[2][1] = fmaf(a4.z, b4.y, acc[2][1]);
            acc[2][2] = fmaf(a4.z, b4.z, acc[2][2]);
            acc[2][3] = fmaf(a4.z, b4.w, acc[2][3]);
            acc[3][0] = fmaf(a4.w, b4.x, acc[3][0]);
            acc[3][1] = fmaf(a4.w, b4.y, acc[3][1]);
            acc[3][2] = fmaf(a4.w, b4.z, acc[3][2]);
            acc[3][3] = fmaf(a4.w, b4.w, acc[3][3]);
        }
        if (kt < 7) {
            const int nb = ((kt + 1) & 1) * 16;
            As[nb + qa * 4 + 0][r0] = pa.x;  As[nb + qa * 4 + 1][r0] = pa.y;
            As[nb + qa * 4 + 2][r0] = pa.z;  As[nb + qa * 4 + 3][r0] = pa.w;
            *(float4*)&Bs[nb + lbk][lbq * 4] = pb;
            __syncthreads();
        }
    }

#pragma unroll
    for (int i = 0; i < 4; i++) {
        float4 o;
        o.x = acc[i][0]; o.y = acc[i][1]; o.z = acc[i][2]; o.w = acc[i][3];
        *(float4*)&C[(bm + tr * 4 + i) * H_ + bn + tc * 4] = o;
    }
}

// ---------------------------------------------------------------------------
extern "C" void kernel_launch(void* const* d_in, const int* in_sizes, int n_in,
                              void* d_out, int out_size) {
    const float* enc = (const float*)d_in[0];   // [16,128,256]
    const float* dec = (const float*)d_in[1];   // [16,128,256]
    const float* Wa  = (const float*)d_in[2];   // [256,256]
    const float* Ua  = (const float*)d_in[3];   // [256,256]
    const float* Va  = (const float*)d_in[4];   // [256,1]

    float* out   = (float*)d_out;
    float* c_out = out;                          // [16,128,256]
    float* e_out = out + B_ * TD_ * H_;          // [16,128,128]

    k1_kernel<<<384, 256>>>(enc, dec, Wa, Ua);
    energy_kernel<<<dim3(TD_ / 4, B_), 512>>>(Va, e_out);
    ctx_kernel<<<dim3(4, 2, 16), 256>>>(e_out, c_out);
}

// round 16
// speedup vs baseline: 1.0326x; 1.0326x over previous
#include <cuda_runtime.h>
#include <cuda_bf16.h>
#include <cuda_fp16.h>
#include <cstdint>

// Problem constants
#define B_   16
#define TE_  128
#define TD_  128
#define H_   256

// Scratch (device globals)
__device__ float g_ortho[B_ * TE_ * H_];   // enc - cumsum_excl(enc)
__device__ float g_was  [B_ * TE_ * H_];   // scanned enc@Wa
__device__ float g_uah  [B_ * TD_ * H_];   // dec @ U_a

__device__ __forceinline__ float tanh_fast(float x) {
    float y;
    asm("tanh.approx.f32 %0, %1;" : "=f"(y) : "f"(x));
    return y;
}

__device__ __forceinline__ void mma_tf32(float c[4],
                                         uint32_t a0, uint32_t a1, uint32_t a2, uint32_t a3,
                                         uint32_t b0, uint32_t b1) {
    asm volatile(
        "mma.sync.aligned.m16n8k8.row.col.f32.tf32.tf32.f32 "
        "{%0,%1,%2,%3}, {%4,%5,%6,%7}, {%8,%9}, {%0,%1,%2,%3};"
        : "+f"(c[0]), "+f"(c[1]), "+f"(c[2]), "+f"(c[3])
        : "r"(a0), "r"(a1), "r"(a2), "r"(a3), "r"(b0), "r"(b1));
}

// Split float into tf32 hi + tf32 lo (3xTF32 accuracy trick)
__device__ __forceinline__ void tf32_split(float x, float& hf, float& lf) {
    uint32_t h;
    asm("cvt.rna.tf32.f32 %0, %1;" : "=r"(h) : "f"(x));
    hf = __uint_as_float(h);
    float l = x - hf;
    uint32_t lo;
    asm("cvt.rna.tf32.f32 %0, %1;" : "=r"(lo) : "f"(l));
    lf = __uint_as_float(lo);
}

// ---------------------------------------------------------------------------
// 512-thread scan unit: out[b,t,hg*32+hl] = in - excl_cumsum_t(in)
// 16 warps; each warp scans 2 h-columns. sm >= 128*33 floats.
// ---------------------------------------------------------------------------
__device__ __forceinline__ void scan_block512(const float* __restrict__ in,
                                              float* __restrict__ out,
                                              int b, int hg, float* sm) {
    const int tid  = threadIdx.x;
    const int warp = tid >> 5;
    const int lane = tid & 31;

    const float* base = in + (b * TE_) * H_ + hg * 32;
#pragma unroll
    for (int k = 0; k < 8; k++) {
        int idx = tid + k * 512;
        int t = idx >> 5, hl = idx & 31;
        sm[t * 33 + hl] = base[t * H_ + hl];
    }
    __syncthreads();

#pragma unroll
    for (int c = 0; c < 2; c++) {
        int h = warp * 2 + c;
        float a0 = sm[(4 * lane + 0) * 33 + h];
        float a1 = sm[(4 * lane + 1) * 33 + h];
        float a2 = sm[(4 * lane + 2) * 33 + h];
        float a3 = sm[(4 * lane + 3) * 33 + h];
        float L = (a0 + a1) + (a2 + a3);
        float sc = L;
#pragma unroll
        for (int o = 1; o < 32; o <<= 1) {
            float v = __shfl_up_sync(0xffffffffu, sc, o);
            if (lane >= o) sc += v;
        }
        float p = sc - L;
        float o0 = a0 - p; p += a0;
        float o1 = a1 - p; p += a1;
        float o2 = a2 - p; p += a2;
        float o3 = a3 - p;
        sm[(4 * lane + 0) * 33 + h] = o0;
        sm[(4 * lane + 1) * 33 + h] = o1;
        sm[(4 * lane + 2) * 33 + h] = o2;
        sm[(4 * lane + 3) * 33 + h] = o3;
    }
    __syncthreads();

    float* obase = out + (b * TE_) * H_ + hg * 32;
#pragma unroll
    for (int k = 0; k < 8; k++) {
        int idx = tid + k * 512;
        int t = idx >> 5, hl = idx & 31;
        obase[t * H_ + hl] = sm[t * 33 + hl];
    }
}

// ---------------------------------------------------------------------------
// K1 (grid dim3(4,16,2), 256 threads): the two tf32 GEMMs ONLY.
//   z=0 -> g_was = scan(enc @ Wa)   (scan over T fused in epilogue)
//   z=1 -> g_uah = dec @ Ua
// 128x64 tile, 8 warps of 32x32, m16n8k8 with 3xTF32 hi/lo split.
// ---------------------------------------------------------------------------
__global__ __launch_bounds__(256) void k1_kernel(const float* __restrict__ enc,
                                                 const float* __restrict__ dec,
                                                 const float* __restrict__ Wa,
                                                 const float* __restrict__ Ua) {
    __shared__ __align__(16) float sm[8320];   // 33.3KB multi-purpose

    const int z = blockIdx.z;
    const float* A = z ? dec : enc;
    const float* W = z ? Ua  : Wa;

    // smem layout (floats): Ah[128][20]@0, Al@2560, Bh[16][72]@5120, Bl@6272
    float* Ah = sm;
    float* Al = sm + 2560;
    float* Bh = sm + 5120;
    float* Bl = sm + 6272;

    const int bm = blockIdx.y * 128;           // batch * 128
    const int bn = blockIdx.x * 64;
    const int tid  = threadIdx.x;
    const int warp = tid >> 5;
    const int lane = tid & 31;
    const int g = lane >> 2;                   // 0..7
    const int t = lane & 3;                    // 0..3
    const int m0 = (warp >> 1) * 32;
    const int n0 = (warp & 1) * 32;

    const int ar  = tid >> 1;                  // A row 0..127
    const int akh = (tid & 1) * 8;
    const int bkr = tid >> 4;                  // B k-row 0..15
    const int bcq = (tid & 15) * 4;

    float acc[2][4][4];
#pragma unroll
    for (int ma = 0; ma < 2; ma++)
#pragma unroll
        for (int na = 0; na < 4; na++)
#pragma unroll
            for (int j = 0; j < 4; j++) acc[ma][na][j] = 0.0f;

    float4 pA0, pA1, pB;
    pA0 = *(const float4*)&A[(bm + ar) * 256 + akh];
    pA1 = *(const float4*)&A[(bm + ar) * 256 + akh + 4];
    pB  = *(const float4*)&W[bkr * 256 + bn + bcq];

    auto sts_tiles = [&](float4 a0v, float4 a1v, float4 bv) {
        float4 h, l;
        tf32_split(a0v.x, h.x, l.x); tf32_split(a0v.y, h.y, l.y);
        tf32_split(a0v.z, h.z, l.z); tf32_split(a0v.w, h.w, l.w);
        *(float4*)&Ah[ar * 20 + akh] = h;  *(float4*)&Al[ar * 20 + akh] = l;
        tf32_split(a1v.x, h.x, l.x); tf32_split(a1v.y, h.y, l.y);
        tf32_split(a1v.z, h.z, l.z); tf32_split(a1v.w, h.w, l.w);
        *(float4*)&Ah[ar * 20 + akh + 4] = h;  *(float4*)&Al[ar * 20 + akh + 4] = l;
        tf32_split(bv.x, h.x, l.x); tf32_split(bv.y, h.y, l.y);
        tf32_split(bv.z, h.z, l.z); tf32_split(bv.w, h.w, l.w);
        *(float4*)&Bh[bkr * 72 + bcq] = h;  *(float4*)&Bl[bkr * 72 + bcq] = l;
    };

    sts_tiles(pA0, pA1, pB);
    __syncthreads();

#pragma unroll 1
    for (int kt = 0; kt < 16; kt++) {
        if (kt < 15) {
            int k0 = (kt + 1) * 16;
            pA0 = *(const float4*)&A[(bm + ar) * 256 + k0 + akh];
            pA1 = *(const float4*)&A[(bm + ar) * 256 + k0 + akh + 4];
            pB  = *(const float4*)&W[(k0 + bkr) * 256 + bn + bcq];
        }
#pragma unroll
        for (int ka = 0; ka < 2; ka++) {
            const int kb = ka * 8 + t;
            uint32_t ah[2][4], al[2][4];
#pragma unroll
            for (int ma = 0; ma < 2; ma++) {
                int r = m0 + ma * 16 + g;
                ah[ma][0] = __float_as_uint(Ah[r * 20 + kb]);
                ah[ma][1] = __float_as_uint(Ah[(r + 8) * 20 + kb]);
                ah[ma][2] = __float_as_uint(Ah[r * 20 + kb + 4]);
                ah[ma][3] = __float_as_uint(Ah[(r + 8) * 20 + kb + 4]);
                al[ma][0] = __float_as_uint(Al[r * 20 + kb]);
                al[ma][1] = __float_as_uint(Al[(r + 8) * 20 + kb]);
                al[ma][2] = __float_as_uint(Al[r * 20 + kb + 4]);
                al[ma][3] = __float_as_uint(Al[(r + 8) * 20 + kb + 4]);
            }
#pragma unroll
            for (int na = 0; na < 4; na++) {
                int n = n0 + na * 8 + g;
                uint32_t bh0 = __float_as_uint(Bh[kb * 72 + n]);
                uint32_t bh1 = __float_as_uint(Bh[(ka * 8 + t + 4) * 72 + n]);
                uint32_t bl0 = __float_as_uint(Bl[kb * 72 + n]);
                uint32_t bl1 = __float_as_uint(Bl[(ka * 8 + t + 4) * 72 + n]);
#pragma unroll
                for (int ma = 0; ma < 2; ma++) {
                    mma_tf32(acc[ma][na], ah[ma][0], ah[ma][1], ah[ma][2], ah[ma][3], bh0, bh1);
                    mma_tf32(acc[ma][na], al[ma][0], al[ma][1], al[ma][2], al[ma][3], bh0, bh1);
                    mma_tf32(acc[ma][na], ah[ma][0], ah[ma][1], ah[ma][2], ah[ma][3], bl0, bl1);
                }
            }
        }
        __syncthreads();
        if (kt < 15) {
            sts_tiles(pA0, pA1, pB);
            __syncthreads();
        }
    }

    if (z == 1) {
#pragma unroll
        for (int ma = 0; ma < 2; ma++)
#pragma unroll
            for (int na = 0; na < 4; na++) {
                int r = bm + m0 + ma * 16 + g;
                int c = bn + n0 + na * 8 + 2 * t;
                float2 lo2 = {acc[ma][na][0], acc[ma][na][1]};
                float2 hi2 = {acc[ma][na][2], acc[ma][na][3]};
                *(float2*)&g_uah[r * 256 + c]       = lo2;
                *(float2*)&g_uah[(r + 8) * 256 + c] = hi2;
            }
        return;
    }

    // z == 0: fused scan epilogue (sb aliases tile buffers, post-sync)
    float* sb = sm;
#pragma unroll
    for (int ma = 0; ma < 2; ma++)
#pragma unroll
        for (int na = 0; na < 4; na++) {
            int r = m0 + ma * 16 + g;
            int c = n0 + na * 8 + 2 * t;
            sb[r * 65 + c]       = acc[ma][na][0];
            sb[r * 65 + c + 1]   = acc[ma][na][1];
            sb[(r + 8) * 65 + c]     = acc[ma][na][2];
            sb[(r + 8) * 65 + c + 1] = acc[ma][na][3];
        }
    __syncthreads();

#pragma unroll
    for (int c = 0; c < 8; c++) {
        int col = warp * 8 + c;
        float a0 = sb[(4 * lane + 0) * 65 + col];
        float a1 = sb[(4 * lane + 1) * 65 + col];
        float a2 = sb[(4 * lane + 2) * 65 + col];
        float a3 = sb[(4 * lane + 3) * 65 + col];
        float L = (a0 + a1) + (a2 + a3);
        float sc = L;
#pragma unroll
        for (int o = 1; o < 32; o <<= 1) {
            float v = __shfl_up_sync(0xffffffffu, sc, o);
            if (lane >= o) sc += v;
        }
        float p = sc - L;
        float o0 = a0 - p; p += a0;
        float o1 = a1 - p; p += a1;
        float o2 = a2 - p; p += a2;
        float o3 = a3 - p;
        sb[(4 * lane + 0) * 65 + col] = o0;
        sb[(4 * lane + 1) * 65 + col] = o1;
        sb[(4 * lane + 2) * 65 + col] = o2;
        sb[(4 * lane + 3) * 65 + col] = o3;
    }
    __syncthreads();

#pragma unroll
    for (int k = 0; k < 32; k++) {
        int idx = tid + k * 256;
        int t2 = idx >> 6, c = idx & 63;
        g_was[(bm + t2) * 256 + bn + c] = sb[t2 * 65 + c];
    }
}

// ---------------------------------------------------------------------------
// K2 (grid dim3(36,16), 512 threads):
//   x < 32: energies + softmax for d0 = x*4 (R13 structure, dual FFMA chains)
//   x >= 32: two g_ortho scan units (hidden under the energy phase —
//            g_ortho is only consumed by ctx_kernel)
// ---------------------------------------------------------------------------
__global__ __launch_bounds__(512) void energy_kernel(const float* __restrict__ enc,
                                                     const float* __restrict__ Va,
                                                     float* __restrict__ e_out) {
    const int b   = blockIdx.y;
    const int bx  = blockIdx.x;
    const int tid = threadIdx.x;

    __shared__ float part[16][16][33];   // also aliased as scan buffer
    __shared__ float en_s[4][TE_];

    if (bx >= 32) {                      // ---- ortho scan duty ----
        int u = bx - 32;                 // 0..3
        float* sm = &part[0][0][0];      // 8448 floats >= 4224 needed
        scan_block512(enc, g_ortho, b, u * 2, sm);
        __syncthreads();
        scan_block512(enc, g_ortho, b, u * 2 + 1, sm);
        return;
    }

    const int d0   = bx * 4;
    const int warp = tid >> 5;
    const int lane = tid & 31;
    const int wd   = warp & 3;
    const int eq   = warp >> 2;

    const int d = d0 + wd;

    const float4 v0 = *(const float4*)(Va + 4 * lane);
    const float4 v1 = *(const float4*)(Va + 128 + 4 * lane);
    const float* urow = g_uah + ((b * TD_) + d) * H_;
    const float4 u0 = *(const float4*)(urow + 4 * lane);
    const float4 u1 = *(const float4*)(urow + 128 + 4 * lane);

    const float* wbase = g_was + (b * TE_) * H_;
    const int ebase = eq * 32;

#pragma unroll
    for (int c0 = 0; c0 < 32; c0 += 16) {
#pragma unroll 4
        for (int el = 0; el < 16; el++) {
            const float* wr = wbase + (ebase + c0 + el) * H_;
            float4 w0 = *(const float4*)(wr + 4 * lane);
            float4 w1 = *(const float4*)(wr + 128 + 4 * lane);
            // dual independent accumulation chains
            float s0 = tanh_fast(w0.x + u0.x) * v0.x;
            float s1 = tanh_fast(w0.y + u0.y) * v0.y;
            s0 = fmaf(tanh_fast(w0.z + u0.z), v0.z, s0);
            s1 = fmaf(tanh_fast(w0.w + u0.w), v0.w, s1);
            s0 = fmaf(tanh_fast(w1.x + u1.x), v1.x, s0);
            s1 = fmaf(tanh_fast(w1.y + u1.y), v1.y, s1);
            s0 = fmaf(tanh_fast(w1.z + u1.z), v1.z, s0);
            s1 = fmaf(tanh_fast(w1.w + u1.w), v1.w, s1);
            part[warp][el][lane] = s0 + s1;
        }
        __syncwarp();
        if (lane < 16) {
            float s = 0.0f;
#pragma unroll
            for (int j = 0; j < 32; j++) s += part[warp][lane][j];
            en_s[wd][ebase + c0 + lane] = s;
        }
        __syncwarp();
    }
    __syncthreads();

    if (warp < 4) {
        float v0s = en_s[wd][lane];
        float v1s = en_s[wd][lane + 32];
        float v2s = en_s[wd][lane + 64];
        float v3s = en_s[wd][lane + 96];
        float m = fmaxf(fmaxf(v0s, v1s), fmaxf(v2s, v3s));
#pragma unroll
        for (int o = 16; o > 0; o >>= 1)
            m = fmaxf(m, __shfl_xor_sync(0xffffffffu, m, o));
        float e0v = __expf(v0s - m), e1v = __expf(v1s - m);
        float e2v = __expf(v2s - m), e3v = __expf(v3s - m);
        float s = e0v + e1v + e2v + e3v;
#pragma unroll
        for (int o = 16; o > 0; o >>= 1)
            s += __shfl_xor_sync(0xffffffffu, s, o);
        float inv = __fdividef(1.0f, s);
        float* eo = e_out + ((b * TD_) + d) * TE_;
        eo[lane]      = e0v * inv;
        eo[lane + 32] = e1v * inv;
        eo[lane + 64] = e2v * inv;
        eo[lane + 96] = e3v * inv;
    }
}

// ---------------------------------------------------------------------------
// K3: context batched GEMM.  c_out[b] = P[b] (TD x TE) @ g_ortho[b] (TE x H)
// ---------------------------------------------------------------------------
__global__ __launch_bounds__(256) void ctx_kernel(const float* __restrict__ P,
                                                  float* __restrict__ c_out) {
    __shared__ __align__(16) float sm2[2 * 16 * 68 * 2];

    float (*As)[68] = (float (*)[68])sm2;
    float (*Bs)[68] = (float (*)[68])(sm2 + 2 * 16 * 68);

    const int bz = blockIdx.z;
    const int bm = blockIdx.y * 64;
    const int bn = blockIdx.x * 64;
    const int tid = threadIdx.x;
    const int tr = tid >> 4;
    const int tc = tid & 15;

    const float* A = P       + bz * TD_ * TE_;
    const float* W = g_ortho + bz * TE_ * H_;
    float*       C = c_out   + bz * TD_ * H_;

    const int r0 = tid >> 2;
    const int qa = tid & 3;
    const int lbk = tid >> 4;
    const int lbq = tid & 15;

    float acc[4][4];
#pragma unroll
    for (int i = 0; i < 4; i++)
#pragma unroll
        for (int j = 0; j < 4; j++) acc[i][j] = 0.0f;

    float4 pa = *(const float4*)&A[(bm + r0) * TE_ + qa * 4];
    float4 pb = *(const float4*)&W[lbk * H_ + bn + lbq * 4];
    As[qa * 4 + 0][r0] = pa.x;  As[qa * 4 + 1][r0] = pa.y;
    As[qa * 4 + 2][r0] = pa.z;  As[qa * 4 + 3][r0] = pa.w;
    *(float4*)&Bs[lbk][lbq * 4] = pb;
    __syncthreads();

#pragma unroll 1
    for (int kt = 0; kt < 8; kt++) {
        if (kt < 7) {
            int k0 = (kt + 1) * 16;
            pa = *(const float4*)&A[(bm + r0) * TE_ + k0 + qa * 4];
            pb = *(const float4*)&W[(k0 + lbk) * H_ + bn + lbq * 4];
        }
        const int cb = (kt & 1) * 16;
#pragma unroll
        for (int kk = 0; kk < 16; kk++) {
            float4 a4 = *(const float4*)&As[cb + kk][tr * 4];
            float4 b4 = *(const float4*)&Bs[cb + kk][tc * 4];
            acc[0][0] = fmaf(a4.x, b4.x, acc[0][0]);
            acc[0][1] = fmaf(a4.x, b4.y, acc[0][1]);
            acc[0][2] = fmaf(a4.x, b4.z, acc[0][2]);
            acc[0][3] = fmaf(a4.x, b4.w, acc[0][3]);
            acc[1][0] = fmaf(a4.y, b4.x, acc[1][0]);
            acc[1][1] = fmaf(a4.y, b4.y, acc[1][1]);
            acc[1][2] = fmaf(a4.y, b4.z, acc[1][2]);
            acc[1][3] = fmaf(a4.y, b4.w, acc[1][3]);
            acc[2][0] = fmaf(a4.z, b4.x, acc[2][0]);
            acc[2][1] = fmaf(a4.z, b4.y, acc[2][1]);
            acc[2][2] = fmaf(a4.z, b4.z, acc[2][2]);
            acc[2][3] = fmaf(a4.z, b4.w, acc[2][3]);
            acc[3][0] = fmaf(a4.w, b4.x, acc[3][0]);
            acc[3][1] = fmaf(a4.w, b4.y, acc[3][1]);
            acc[3][2] = fmaf(a4.w, b4.z, acc[3][2]);
            acc[3][3] = fmaf(a4.w, b4.w, acc[3][3]);
        }
        if (kt < 7) {
            const int nb = ((kt + 1) & 1) * 16;
            As[nb + qa * 4 + 0][r0] = pa.x;  As[nb + qa * 4 + 1][r0] = pa.y;
            As[nb + qa * 4 + 2][r0] = pa.z;  As[nb + qa * 4 + 3][r0] = pa.w;
            *(float4*)&Bs[nb + lbk][lbq * 4] = pb;
            __syncthreads();
        }
    }

#pragma unroll
    for (int i = 0; i < 4; i++) {
        float4 o;
        o.x = acc[i][0]; o.y = acc[i][1]; o.z = acc[i][2]; o.w = acc[i][3];
        *(float4*)&C[(bm + tr * 4 + i) * H_ + bn + tc * 4] = o;
    }
}

// ---------------------------------------------------------------------------
extern "C" void kernel_launch(void* const* d_in, const int* in_sizes, int n_in,
                              void* d_out, int out_size) {
    const float* enc = (const float*)d_in[0];   // [16,128,256]
    const float* dec = (const float*)d_in[1];   // [16,128,256]
    const float* Wa  = (const float*)d_in[2];   // [256,256]
    const float* Ua  = (const float*)d_in[3];   // [256,256]
    const float* Va  = (const float*)d_in[4];   // [256,1]

    float* out   = (float*)d_out;
    float* c_out = out;                          // [16,128,256]
    float* e_out = out + B_ * TD_ * H_;          // [16,128,128]

    k1_kernel<<<dim3(4, 16, 2), 256>>>(enc, dec, Wa, Ua);
    energy_kernel<<<dim3(36, 16), 512>>>(enc, Va, e_out);
    ctx_kernel<<<dim3(4, 2, 16), 256>>>(e_out, c_out);
}

// round 17
// speedup vs baseline: 1.0733x; 1.0394x over previous
#include <cuda_runtime.h>
#include <cuda_bf16.h>
#include <cuda_fp16.h>
#include <cstdint>

// Problem constants
#define B_   16
#define TE_  128
#define TD_  128
#define H_   256

// Scratch (device globals)
__device__ float g_ortho[B_ * TE_ * H_];   // enc - cumsum_excl(enc)
__device__ float g_was  [B_ * TE_ * H_];   // scanned enc@Wa
__device__ float g_uah  [B_ * TD_ * H_];   // dec @ U_a
__device__ int   g_flags[B_];              // per-batch producer counters (8 = ready)

__device__ __forceinline__ float tanh_fast(float x) {
    float y;
    asm("tanh.approx.f32 %0, %1;" : "=f"(y) : "f"(x));
    return y;
}

__device__ __forceinline__ void mma_tf32(float c[4],
                                         uint32_t a0, uint32_t a1, uint32_t a2, uint32_t a3,
                                         uint32_t b0, uint32_t b1) {
    asm volatile(
        "mma.sync.aligned.m16n8k8.row.col.f32.tf32.tf32.f32 "
        "{%0,%1,%2,%3}, {%4,%5,%6,%7}, {%8,%9}, {%0,%1,%2,%3};"
        : "+f"(c[0]), "+f"(c[1]), "+f"(c[2]), "+f"(c[3])
        : "r"(a0), "r"(a1), "r"(a2), "r"(a3), "r"(b0), "r"(b1));
}

__device__ __forceinline__ void tf32_split(float x, float& hf, float& lf) {
    uint32_t h;
    asm("cvt.rna.tf32.f32 %0, %1;" : "=r"(h) : "f"(x));
    hf = __uint_as_float(h);
    float l = x - hf;
    uint32_t lo;
    asm("cvt.rna.tf32.f32 %0, %1;" : "=r"(lo) : "f"(l));
    lf = __uint_as_float(lo);
}

// ---------------------------------------------------------------------------
// 256-thread scan unit: out[b,t,hg*32+hl] = in - excl_cumsum_t(in)
// ---------------------------------------------------------------------------
__device__ __forceinline__ void scan_block(const float* __restrict__ in,
                                           float* __restrict__ out,
                                           int b, int hg, float* sm) {
    const int tid  = threadIdx.x;
    const int warp = tid >> 5;
    const int lane = tid & 31;

    const float* base = in + (b * TE_) * H_ + hg * 32;
#pragma unroll
    for (int k = 0; k < 16; k++) {
        int idx = tid + k * 256;
        int t = idx >> 5, hl = idx & 31;
        sm[t * 33 + hl] = base[t * H_ + hl];
    }
    __syncthreads();

#pragma unroll
    for (int c = 0; c < 4; c++) {
        int h = warp * 4 + c;
        float a0 = sm[(4 * lane + 0) * 33 + h];
        float a1 = sm[(4 * lane + 1) * 33 + h];
        float a2 = sm[(4 * lane + 2) * 33 + h];
        float a3 = sm[(4 * lane + 3) * 33 + h];
        float L = (a0 + a1) + (a2 + a3);
        float sc = L;
#pragma unroll
        for (int o = 1; o < 32; o <<= 1) {
            float v = __shfl_up_sync(0xffffffffu, sc, o);
            if (lane >= o) sc += v;
        }
        float p = sc - L;
        float o0 = a0 - p; p += a0;
        float o1 = a1 - p; p += a1;
        float o2 = a2 - p; p += a2;
        float o3 = a3 - p;
        sm[(4 * lane + 0) * 33 + h] = o0;
        sm[(4 * lane + 1) * 33 + h] = o1;
        sm[(4 * lane + 2) * 33 + h] = o2;
        sm[(4 * lane + 3) * 33 + h] = o3;
    }
    __syncthreads();

    float* obase = out + (b * TE_) * H_ + hg * 32;
#pragma unroll
    for (int k = 0; k < 16; k++) {
        int idx = tid + k * 256;
        int t = idx >> 5, hl = idx & 31;
        obase[t * H_ + hl] = sm[t * 33 + hl];
    }
}

// ---------------------------------------------------------------------------
// FUSED kernel, 1-D grid of 1216 x 256 threads:
//   bid [0,64):     g_was = scan(enc @ Wa)  -> atomicAdd(flag[b])
//   bid [64,128):   g_uah = dec @ Ua        -> atomicAdd(flag[b])
//   bid [128,192):  g_ortho scans (2 units each; consumed only by ctx)
//   bid [192,1216): energy+softmax, waits for flag[b]==8
// ---------------------------------------------------------------------------
__global__ __launch_bounds__(256) void fused_kernel(const float* __restrict__ enc,
                                                    const float* __restrict__ dec,
                                                    const float* __restrict__ Wa,
                                                    const float* __restrict__ Ua,
                                                    const float* __restrict__ Va,
                                                    float* __restrict__ e_out) {
    __shared__ __align__(16) float sm[8448];   // 33.8KB multi-purpose
    const int bid = blockIdx.x;
    const int tid = threadIdx.x;

    // ======================= ortho scans =======================
    if (bid >= 128 && bid < 192) {
        int lin = bid - 128;                   // 0..63
        scan_block(enc, g_ortho, lin >> 3, lin & 7, sm);
        __syncthreads();
        int lin2 = lin + 64;
        scan_block(enc, g_ortho, lin2 >> 3, lin2 & 7, sm);
        return;
    }

    // ======================= energy consumers =======================
    if (bid >= 192) {
        const int local = bid - 192;           // 0..1023
        const int b  = local >> 6;             // batch
        const int d0 = (local & 63) * 2;       // 2 d per block
        const int warp = tid >> 5;
        const int lane = tid & 31;
        const int wd   = warp & 1;             // which d
        const int eq   = warp >> 1;            // e-quarter 0..3

        float* part = sm;                      // [8][16][33] = 4224
        float* en_s = sm + 4224;               // [2][128]

        const int d = d0 + wd;

        const float4 v0 = *(const float4*)(Va + 4 * lane);
        const float4 v1 = *(const float4*)(Va + 128 + 4 * lane);

        // Wait for this batch's 8 GEMM producer blocks
        if (tid == 0) {
            while (*(volatile int*)&g_flags[b] < 8) __nanosleep(100);
        }
        __syncthreads();
        __threadfence();

        const float* urow = g_uah + ((b * TD_) + d) * H_;
        const float4 u0 = *(const float4*)(urow + 4 * lane);
        const float4 u1 = *(const float4*)(urow + 128 + 4 * lane);

        const float* wbase = g_was + (b * TE_) * H_;
        const int ebase = eq * 32;

#pragma unroll
        for (int c0 = 0; c0 < 32; c0 += 16) {
#pragma unroll 4
            for (int el = 0; el < 16; el++) {
                const float* wr = wbase + (ebase + c0 + el) * H_;
                float4 w0 = *(const float4*)(wr + 4 * lane);
                float4 w1 = *(const float4*)(wr + 128 + 4 * lane);
                float s = tanh_fast(w0.x + u0.x) * v0.x;
                s = fmaf(tanh_fast(w0.y + u0.y), v0.y, s);
                s = fmaf(tanh_fast(w0.z + u0.z), v0.z, s);
                s = fmaf(tanh_fast(w0.w + u0.w), v0.w, s);
                s = fmaf(tanh_fast(w1.x + u1.x), v1.x, s);
                s = fmaf(tanh_fast(w1.y + u1.y), v1.y, s);
                s = fmaf(tanh_fast(w1.z + u1.z), v1.z, s);
                s = fmaf(tanh_fast(w1.w + u1.w), v1.w, s);
                part[(warp * 16 + el) * 33 + lane] = s;
            }
            __syncwarp();
            if (lane < 16) {
                float s = 0.0f;
#pragma unroll
                for (int j = 0; j < 32; j++) s += part[(warp * 16 + lane) * 33 + j];
                en_s[wd * TE_ + ebase + c0 + lane] = s;
            }
            __syncwarp();
        }
        __syncthreads();

        // Softmax (warps 0-1, one d each)
        if (warp < 2) {
            float v0s = en_s[warp * TE_ + lane];
            float v1s = en_s[warp * TE_ + lane + 32];
            float v2s = en_s[warp * TE_ + lane + 64];
            float v3s = en_s[warp * TE_ + lane + 96];
            float m = fmaxf(fmaxf(v0s, v1s), fmaxf(v2s, v3s));
#pragma unroll
            for (int o = 16; o > 0; o >>= 1)
                m = fmaxf(m, __shfl_xor_sync(0xffffffffu, m, o));
            float e0v = __expf(v0s - m), e1v = __expf(v1s - m);
            float e2v = __expf(v2s - m), e3v = __expf(v3s - m);
            float s = e0v + e1v + e2v + e3v;
#pragma unroll
            for (int o = 16; o > 0; o >>= 1)
                s += __shfl_xor_sync(0xffffffffu, s, o);
            float inv = __fdividef(1.0f, s);
            float* eo = e_out + ((b * TD_) + (d0 + warp)) * TE_;
            eo[lane]      = e0v * inv;
            eo[lane + 32] = e1v * inv;
            eo[lane + 64] = e2v * inv;
            eo[lane + 96] = e3v * inv;
        }
        return;
    }

    // ======================= GEMM producers (bid < 128) =======================
    const int z = (bid >= 64) ? 1 : 0;
    const int local = bid & 63;
    const int b  = local >> 2;
    const int bm = b * 128;
    const int bn = (local & 3) * 64;
    const float* A = z ? dec : enc;
    const float* W = z ? Ua  : Wa;

    float* Ah = sm;
    float* Al = sm + 2560;
    float* Bh = sm + 5120;
    float* Bl = sm + 6272;

    const int warp = tid >> 5;
    const int lane = tid & 31;
    const int g = lane >> 2;
    const int t = lane & 3;
    const int m0 = (warp >> 1) * 32;
    const int n0 = (warp & 1) * 32;

    const int ar  = tid >> 1;
    const int akh = (tid & 1) * 8;
    const int bkr = tid >> 4;
    const int bcq = (tid & 15) * 4;

    float acc[2][4][4];
#pragma unroll
    for (int ma = 0; ma < 2; ma++)
#pragma unroll
        for (int na = 0; na < 4; na++)
#pragma unroll
            for (int j = 0; j < 4; j++) acc[ma][na][j] = 0.0f;

    float4 pA0, pA1, pB;
    pA0 = *(const float4*)&A[(bm + ar) * 256 + akh];
    pA1 = *(const float4*)&A[(bm + ar) * 256 + akh + 4];
    pB  = *(const float4*)&W[bkr * 256 + bn + bcq];

    auto sts_tiles = [&](float4 a0v, float4 a1v, float4 bv) {
        float4 h, l;
        tf32_split(a0v.x, h.x, l.x); tf32_split(a0v.y, h.y, l.y);
        tf32_split(a0v.z, h.z, l.z); tf32_split(a0v.w, h.w, l.w);
        *(float4*)&Ah[ar * 20 + akh] = h;  *(float4*)&Al[ar * 20 + akh] = l;
        tf32_split(a1v.x, h.x, l.x); tf32_split(a1v.y, h.y, l.y);
        tf32_split(a1v.z, h.z, l.z); tf32_split(a1v.w, h.w, l.w);
        *(float4*)&Ah[ar * 20 + akh + 4] = h;  *(float4*)&Al[ar * 20 + akh + 4] = l;
        tf32_split(bv.x, h.x, l.x); tf32_split(bv.y, h.y, l.y);
        tf32_split(bv.z, h.z, l.z); tf32_split(bv.w, h.w, l.w);
        *(float4*)&Bh[bkr * 72 + bcq] = h;  *(float4*)&Bl[bkr * 72 + bcq] = l;
    };

    sts_tiles(pA0, pA1, pB);
    __syncthreads();

#pragma unroll 1
    for (int kt = 0; kt < 16; kt++) {
        if (kt < 15) {
            int k0 = (kt + 1) * 16;
            pA0 = *(const float4*)&A[(bm + ar) * 256 + k0 + akh];
            pA1 = *(const float4*)&A[(bm + ar) * 256 + k0 + akh + 4];
            pB  = *(const float4*)&W[(k0 + bkr) * 256 + bn + bcq];
        }
#pragma unroll
        for (int ka = 0; ka < 2; ka++) {
            const int kb = ka * 8 + t;
            uint32_t ah[2][4], al[2][4];
#pragma unroll
            for (int ma = 0; ma < 2; ma++) {
                int r = m0 + ma * 16 + g;
                ah[ma][0] = __float_as_uint(Ah[r * 20 + kb]);
                ah[ma][1] = __float_as_uint(Ah[(r + 8) * 20 + kb]);
                ah[ma][2] = __float_as_uint(Ah[r * 20 + kb + 4]);
                ah[ma][3] = __float_as_uint(Ah[(r + 8) * 20 + kb + 4]);
                al[ma][0] = __float_as_uint(Al[r * 20 + kb]);
                al[ma][1] = __float_as_uint(Al[(r + 8) * 20 + kb]);
                al[ma][2] = __float_as_uint(Al[r * 20 + kb + 4]);
                al[ma][3] = __float_as_uint(Al[(r + 8) * 20 + kb + 4]);
            }
#pragma unroll
            for (int na = 0; na < 4; na++) {
                int n = n0 + na * 8 + g;
                uint32_t bh0 = __float_as_uint(Bh[kb * 72 + n]);
                uint32_t bh1 = __float_as_uint(Bh[(ka * 8 + t + 4) * 72 + n]);
                uint32_t bl0 = __float_as_uint(Bl[kb * 72 + n]);
                uint32_t bl1 = __float_as_uint(Bl[(ka * 8 + t + 4) * 72 + n]);
#pragma unroll
                for (int ma = 0; ma < 2; ma++) {
                    mma_tf32(acc[ma][na], ah[ma][0], ah[ma][1], ah[ma][2], ah[ma][3], bh0, bh1);
                    mma_tf32(acc[ma][na], al[ma][0], al[ma][1], al[ma][2], al[ma][3], bh0, bh1);
                    mma_tf32(acc[ma][na], ah[ma][0], ah[ma][1], ah[ma][2], ah[ma][3], bl0, bl1);
                }
            }
        }
        __syncthreads();
        if (kt < 15) {
            sts_tiles(pA0, pA1, pB);
            __syncthreads();
        }
    }

    if (z == 1) {
#pragma unroll
        for (int ma = 0; ma < 2; ma++)
#pragma unroll
            for (int na = 0; na < 4; na++) {
                int r = bm + m0 + ma * 16 + g;
                int c = bn + n0 + na * 8 + 2 * t;
                float2 lo2 = {acc[ma][na][0], acc[ma][na][1]};
                float2 hi2 = {acc[ma][na][2], acc[ma][na][3]};
                *(float2*)&g_uah[r * 256 + c]       = lo2;
                *(float2*)&g_uah[(r + 8) * 256 + c] = hi2;
            }
        __threadfence();
        __syncthreads();
        if (tid == 0) atomicAdd(&g_flags[b], 1);
        return;
    }

    // z == 0: fused scan epilogue, then signal
    float* sb = sm;
#pragma unroll
    for (int ma = 0; ma < 2; ma++)
#pragma unroll
        for (int na = 0; na < 4; na++) {
            int r = m0 + ma * 16 + g;
            int c = n0 + na * 8 + 2 * t;
            sb[r * 65 + c]       = acc[ma][na][0];
            sb[r * 65 + c + 1]   = acc[ma][na][1];
            sb[(r + 8) * 65 + c]     = acc[ma][na][2];
            sb[(r + 8) * 65 + c + 1] = acc[ma][na][3];
        }
    __syncthreads();

#pragma unroll
    for (int c = 0; c < 8; c++) {
        int col = warp * 8 + c;
        float a0 = sb[(4 * lane + 0) * 65 + col];
        float a1 = sb[(4 * lane + 1) * 65 + col];
        float a2 = sb[(4 * lane + 2) * 65 + col];
        float a3 = sb[(4 * lane + 3) * 65 + col];
        float L = (a0 + a1) + (a2 + a3);
        float sc = L;
#pragma unroll
        for (int o = 1; o < 32; o <<= 1) {
            float v = __shfl_up_sync(0xffffffffu, sc, o);
            if (lane >= o) sc += v;
        }
        float p = sc - L;
        float o0 = a0 - p; p += a0;
        float o1 = a1 - p; p += a1;
        float o2 = a2 - p; p += a2;
        float o3 = a3 - p;
        sb[(4 * lane + 0) * 65 + col] = o0;
        sb[(4 * lane + 1) * 65 + col] = o1;
        sb[(4 * lane + 2) * 65 + col] = o2;
        sb[(4 * lane + 3) * 65 + col] = o3;
    }
    __syncthreads();

#pragma unroll
    for (int k = 0; k < 32; k++) {
        int idx = tid + k * 256;
        int t2 = idx >> 6, c = idx & 63;
        g_was[(bm + t2) * 256 + bn + c] = sb[t2 * 65 + c];
    }
    __threadfence();
    __syncthreads();
    if (tid == 0) atomicAdd(&g_flags[b], 1);
}

// ---------------------------------------------------------------------------
// ctx: context batched GEMM.  c_out[b] = P[b] (TD x TE) @ g_ortho[b] (TE x H)
// Block (0,0,0) also resets the producer flags for the next graph replay.
// ---------------------------------------------------------------------------
__global__ __launch_bounds__(256) void ctx_kernel(const float* __restrict__ P,
                                                  float* __restrict__ c_out) {
    __shared__ __align__(16) float sm2[2 * 16 * 68 * 2];

    if (blockIdx.x == 0 && blockIdx.y == 0 && blockIdx.z == 0 && threadIdx.x < B_)
        g_flags[threadIdx.x] = 0;

    float (*As)[68] = (float (*)[68])sm2;
    float (*Bs)[68] = (float (*)[68])(sm2 + 2 * 16 * 68);

    const int bz = blockIdx.z;
    const int bm = blockIdx.y * 64;
    const int bn = blockIdx.x * 64;
    const int tid = threadIdx.x;
    const int tr = tid >> 4;
    const int tc = tid & 15;

    const float* A = P       + bz * TD_ * TE_;
    const float* W = g_ortho + bz * TE_ * H_;
    float*       C = c_out   + bz * TD_ * H_;

    const int r0 = tid >> 2;
    const int qa = tid & 3;
    const int lbk = tid >> 4;
    const int lbq = tid & 15;

    float acc[4][4];
#pragma unroll
    for (int i = 0; i < 4; i++)
#pragma unroll
        for (int j = 0; j < 4; j++) acc[i][j] = 0.0f;

    float4 pa = *(const float4*)&A[(bm + r0) * TE_ + qa * 4];
    float4 pb = *(const float4*)&W[lbk * H_ + bn + lbq * 4];
    As[qa * 4 + 0][r0] = pa.x;  As[qa * 4 + 1][r0] = pa.y;
    As[qa * 4 + 2][r0] = pa.z;  As[qa * 4 + 3][r0] = pa.w;
    *(float4*)&Bs[lbk][lbq * 4] = pb;
    __syncthreads();

#pragma unroll 1
    for (int kt = 0; kt < 8; kt++) {
        if (kt < 7) {
            int k0 = (kt + 1) * 16;
            pa = *(const float4*)&A[(bm + r0) * TE_ + k0 + qa * 4];
            pb = *(const float4*)&W[(k0 + lbk) * H_ + bn + lbq * 4];
        }
        const int cb = (kt & 1) * 16;
#pragma unroll
        for (int kk = 0; kk < 16; kk++) {
            float4 a4 = *(const float4*)&As[cb + kk][tr * 4];
            float4 b4 = *(const float4*)&Bs[cb + kk][tc * 4];
            acc[0][0] = fmaf(a4.x, b4.x, acc[0][0]);
            acc[0][1] = fmaf(a4.x, b4.y, acc[0][1]);
            acc[0][2] = fmaf(a4.x, b4.z, acc[0][2]);
            acc[0][3] = fmaf(a4.x, b4.w, acc[0][3]);
            acc[1][0] = fmaf(a4.y, b4.x, acc[1][0]);
            acc[1][1] = fmaf(a4.y, b4.y, acc[1][1]);
            acc[1][2] = fmaf(a4.y, b4.z, acc[1][2]);
            acc[1][3] = fmaf(a4.y, b4.w, acc[1][3]);
            acc[2][0] = fmaf(a4.z, b4.x, acc[2][0]);
            acc[2][1] = fmaf(a4.z, b4.y, acc[2][1]);
            acc[2][2] = fmaf(a4.z, b4.z, acc[2][2]);
            acc[2][3] = fmaf(a4.z, b4.w, acc[2][3]);
            acc[3][0] = fmaf(a4.w, b4.x, acc[3][0]);
            acc[3][1] = fmaf(a4.w, b4.y, acc[3][1]);
            acc[3][2] = fmaf(a4.w, b4.z, acc[3][2]);
            acc[3][3] = fmaf(a4.w, b4.w, acc[3][3]);
        }
        if (kt < 7) {
            const int nb = ((kt + 1) & 1) * 16;
            As[nb + qa * 4 + 0][r0] = pa.x;  As[nb + qa * 4 + 1][r0] = pa.y;
            As[nb + qa * 4 + 2][r0] = pa.z;  As[nb + qa * 4 + 3][r0] = pa.w;
            *(float4*)&Bs[nb + lbk][lbq * 4] = pb;
            __syncthreads();
        }
    }

#pragma unroll
    for (int i = 0; i < 4; i++) {
        float4 o;
        o.x = acc[i][0]; o.y = acc[i][1]; o.z = acc[i][2]; o.w = acc[i][3];
        *(float4*)&C[(bm + tr * 4 + i) * H_ + bn + tc * 4] = o;
    }
}

// ---------------------------------------------------------------------------
extern "C" void kernel_launch(void* const* d_in, const int* in_sizes, int n_in,
                              void* d_out, int out_size) {
    const float* enc = (const float*)d_in[0];   // [16,128,256]
    const float* dec = (const float*)d_in[1];   // [16,128,256]
    const float* Wa  = (const float*)d_in[2];   // [256,256]
    const float* Ua  = (const float*)d_in[3];   // [256,256]
    const float* Va  = (const float*)d_in[4];   // [256,1]

    float* out   = (float*)d_out;
    float* c_out = out;                          // [16,128,256]
    float* e_out = out + B_ * TD_ * H_;          // [16,128,128]

    fused_kernel<<<1216, 256>>>(enc, dec, Wa, Ua, Va, e_out);
    ctx_kernel<<<dim3(4, 2, 16), 256>>>(e_out, c_out);
}